// round 4
// baseline (speedup 1.0000x reference)
#include <cuda_runtime.h>
#include <cuda_bf16.h>
#include <cstdint>

#define FULLMASK 0xffffffffu
#define F_DIM 1024
#define C_DIM 64
#define N_ROWS 65536           // 32*2048
#define ROWS_PER_BLOCK 8
#define N_BLOCKS (N_ROWS / ROWS_PER_BLOCK)   // 8192
#define PADROW 3008            // 1024 + 63*31 worst-case padding, multiple of 32

// ---- scratch (device globals; no allocation) ----
__device__ __align__(16) int g_permpos[F_DIM];  // f -> padded sorted position
__device__ int g_base[C_DIM];                   // segment -> padded base offset
__device__ int g_len[C_DIM];                    // segment -> length
__device__ int g_segA[32];                      // lane -> segment id (phase A: ranks 0..31)
__device__ int g_segB[32];                      // lane -> segment id (phase B: ranks 63..32)
__device__ int g_maxA, g_maxB;                  // max segment length per phase
__device__ int g_labIsA;                        // 1 if candidate A is the labels buffer
__device__ int g_lab64;                         // 1 if labels are 64-bit
__device__ double g_partials[N_BLOCKS];

// ============================================================
// Detect: disambiguate labels vs mask among the two 65536-elem
// buffers, and label width (int32 vs int64). One block.
//   mask one-hot: ~98% zero words. int64 labels: ~51% (high words).
//   int32 labels: ~1.6%. Odd-word OR == 0  <=>  int64 labels.
// ============================================================
__global__ void detect_kernel(const unsigned* __restrict__ A,
                              const unsigned* __restrict__ B) {
    __shared__ int sh[32];
    int t = threadIdx.x, lane = t & 31, wid = t >> 5;

    int zA = 0, zB = 0;
    unsigned oA = 0u, oB = 0u;
    for (int i = t; i < 8192; i += 1024) {
        unsigned wa = A[i], wb = B[i];
        zA += (wa == 0u); zB += (wb == 0u);
        if (i & 1) { oA |= wa; oB |= wb; }
    }
#pragma unroll
    for (int o = 16; o; o >>= 1) {
        zA += __shfl_xor_sync(FULLMASK, zA, o);
        zB += __shfl_xor_sync(FULLMASK, zB, o);
        oA |= __shfl_xor_sync(FULLMASK, oA, o);
        oB |= __shfl_xor_sync(FULLMASK, oB, o);
    }
    // block combine via smem (4 rounds, reuse sh)
    if (lane == 0) sh[wid] = zA;
    __syncthreads();
    if (t == 0) { int s = 0; for (int i = 0; i < 32; i++) s += sh[i]; sh[0] = s; }
    __syncthreads();
    int zAt = sh[0];
    __syncthreads();
    if (lane == 0) sh[wid] = zB;
    __syncthreads();
    if (t == 0) { int s = 0; for (int i = 0; i < 32; i++) s += sh[i]; sh[0] = s; }
    __syncthreads();
    int zBt = sh[0];
    __syncthreads();
    if (lane == 0) sh[wid] = (int)(oA != 0u);
    __syncthreads();
    if (t == 0) { int s = 0; for (int i = 0; i < 32; i++) s |= sh[i]; sh[0] = s; }
    __syncthreads();
    int oAt = sh[0];
    __syncthreads();
    if (lane == 0) sh[wid] = (int)(oB != 0u);
    __syncthreads();
    if (t == 0) { int s = 0; for (int i = 0; i < 32; i++) s |= sh[i]; sh[0] = s; }
    __syncthreads();
    int oBt = sh[0];

    if (t == 0) {
        int aIsMask = (zAt > 6000);           // mask ~8064 zero words of 8192
        g_labIsA = aIsMask ? 0 : 1;
        int labOdd = aIsMask ? oBt : oAt;     // odd-word OR of the labels buffer
        g_lab64 = (labOdd == 0) ? 1 : 0;      // high words all zero => int64
    }
}

// ============================================================
// Setup: seg ids, counts, length-sorted order, bank-aligned padded
// layout, deterministic scatter permutation. One block, 1024 threads.
// ============================================================
__global__ void setup_kernel(const float* __restrict__ candA,
                             const float* __restrict__ candB) {
    __shared__ int sh_seg[F_DIM];
    __shared__ int sh_cnt[C_DIM];
    __shared__ int sh_order[C_DIM];
    __shared__ int sh_base[C_DIM];

    const float* mask = g_labIsA ? candB : candA;

    int tid = threadIdx.x;
    if (tid < C_DIM) sh_cnt[tid] = 0;
    __syncthreads();

    int wid = tid >> 5, lane = tid & 31;
    // warp per fine row of mask: find the one-hot column via ballot
    for (int f = wid; f < F_DIM; f += 32) {
        float v0 = mask[f * C_DIM + lane];
        float v1 = mask[f * C_DIM + 32 + lane];
        unsigned b0 = __ballot_sync(FULLMASK, v0 > 0.5f);
        unsigned b1 = __ballot_sync(FULLMASK, v1 > 0.5f);
        int c = b0 ? (__ffs(b0) - 1) : (32 + __ffs(b1) - 1);
        if (lane == 0) { sh_seg[f] = c; atomicAdd(&sh_cnt[c], 1); }
    }
    __syncthreads();

    // rank segments by length desc (stable)
    if (tid < C_DIM) {
        int mylen = sh_cnt[tid];
        int r = 0;
        for (int c = 0; c < C_DIM; c++) {
            int lc = sh_cnt[c];
            if (lc > mylen || (lc == mylen && c < tid)) r++;
        }
        sh_order[r] = tid;
    }
    __syncthreads();

    // bases in rank order; rank i start aligned so base % 32 == i % 32
    if (tid == 0) {
        int b = 0;
        for (int i = 0; i < C_DIM; i++) {
            int c = sh_order[i];
            int pad = ((i & 31) - (b & 31) + 32) & 31;
            int bb = b + pad;
            sh_base[c] = bb;
            b = bb + sh_cnt[c];
        }
    }
    __syncthreads();

    // deterministic scatter positions
    if (tid < C_DIM) {
        int p = sh_base[tid];
        for (int f = 0; f < F_DIM; f++) {
            if (sh_seg[f] == tid) g_permpos[f] = p++;
        }
        g_base[tid] = sh_base[tid];
        g_len[tid]  = sh_cnt[tid];
    }
    if (tid < 32) {
        g_segA[tid] = sh_order[tid];
        g_segB[tid] = sh_order[63 - tid];
    }
    if (tid == 0) {
        g_maxA = sh_cnt[sh_order[0]];
        g_maxB = sh_cnt[sh_order[32]];
    }
}

// ============================================================
// Main: 1 warp = 1 row. Stage 4KB row into padded-sorted smem,
// conflict-free segmented max + exp-sum, warp reductions.
// ============================================================
__global__ void __launch_bounds__(256, 2)
main_kernel(const float* __restrict__ logits,
            const void* __restrict__ candA, const void* __restrict__ candB) {
    extern __shared__ float sm[];
    __shared__ float sh_term[ROWS_PER_BLOCK];

    int w = threadIdx.x >> 5, lane = threadIdx.x & 31;
    int row = blockIdx.x * ROWS_PER_BLOCK + w;
    float* buf = sm + w * PADROW;
    const float* src = logits + (size_t)row * F_DIM;

    // label pointer selection from detect flags
    const void* labp = g_labIsA ? candA : candB;
    int labi = g_lab64 ? (int)((const long long*)labp)[row]
                       : ((const int*)labp)[row];

    // hoist descriptor loads so they overlap staging
    int cA = g_segA[lane], cB = g_segB[lane];
    int bA = g_base[cA], lA = g_len[cA];
    int bB = g_base[cB], lB = g_len[cB];
    int LA = g_maxA,    LB = g_maxB;

    // stage: coalesced LDG.128, scatter into padded sorted layout
#pragma unroll
    for (int k = 0; k < 8; k++) {
        int f0 = k * 128 + lane * 4;
        float4 v = *reinterpret_cast<const float4*>(src + f0);
        int4  p = *reinterpret_cast<const int4*>(g_permpos + f0);
        buf[p.x] = v.x; buf[p.y] = v.y; buf[p.z] = v.z; buf[p.w] = v.w;
    }
    __syncwarp();

    // pass 1: per-segment max (bases distinct mod 32 per phase -> conflict-free)
    float mA = -3.4e38f, mB = -3.4e38f;
#pragma unroll 4
    for (int i = 0; i < LA; i++) if (i < lA) mA = fmaxf(mA, buf[bA + i]);
#pragma unroll 4
    for (int i = 0; i < LB; i++) if (i < lB) mB = fmaxf(mB, buf[bB + i]);

    float m = fmaxf(mA, mB);
#pragma unroll
    for (int o = 16; o; o >>= 1) m = fmaxf(m, __shfl_xor_sync(FULLMASK, m, o));

    // pass 2: per-segment sum of exp(v - m)
    float sA = 0.f, sB = 0.f;
#pragma unroll 4
    for (int i = 0; i < LA; i++) if (i < lA) sA += __expf(buf[bA + i] - m);
#pragma unroll 4
    for (int i = 0; i < LB; i++) if (i < lB) sB += __expf(buf[bB + i] - m);

    float e  = sA + sB;                          // Z (shifted)
    float gg = __expf(mA - m) + __expf(mB - m);  // sum_c exp(cmax-m)
    float cl = (cA == labi) ? mA : ((cB == labi) ? mB : -3.4e38f);
    float sl = (cA == labi) ? sA : ((cB == labi) ? sB : 0.f);

#pragma unroll
    for (int o = 16; o; o >>= 1) {
        e  += __shfl_xor_sync(FULLMASK, e, o);
        gg += __shfl_xor_sync(FULLMASK, gg, o);
        cl  = fmaxf(cl, __shfl_xor_sync(FULLMASK, cl, o));
        sl += __shfl_xor_sync(FULLMASK, sl, o);
    }

    if (lane == 0) {
        float term = (cl - m - __logf(gg)) + (__logf(sl) - __logf(e));
        sh_term[w] = term;
    }
    __syncthreads();
    if (threadIdx.x == 0) {
        double t = 0.0;
#pragma unroll
        for (int i = 0; i < ROWS_PER_BLOCK; i++) t += (double)sh_term[i];
        g_partials[blockIdx.x] = t;
    }
}

// ============================================================
// Finish: deterministic reduce of partials -> scalar
// ============================================================
__global__ void finish_kernel(float* __restrict__ out) {
    __shared__ double sh[256];
    int t = threadIdx.x;
    double s = 0.0;
    for (int i = t; i < N_BLOCKS; i += 256) s += g_partials[i];
    sh[t] = s;
    __syncthreads();
    for (int o = 128; o; o >>= 1) {
        if (t < o) sh[t] += sh[t + o];
        __syncthreads();
    }
    if (t == 0) out[0] = (float)(-0.5 * sh[0] / (double)N_ROWS);
}

extern "C" void kernel_launch(void* const* d_in, const int* in_sizes, int n_in,
                              void* d_out, int out_size) {
    // identify logits by element count; the other two are ambiguous on host
    int li = 0;
    for (int i = 0; i < n_in; i++) if (in_sizes[i] > 1000000) { li = i; break; }
    int o1 = (li == 0) ? 1 : 0;
    int o2 = (li == 2) ? 1 : 2;
    if (o2 == o1) o2 = (o1 == 1) ? 2 : 1;

    const float* logits = (const float*)d_in[li];
    const void*  candA  = d_in[o1];
    const void*  candB  = d_in[o2];
    float*       out    = (float*)d_out;

    cudaFuncSetAttribute(main_kernel, cudaFuncAttributeMaxDynamicSharedMemorySize,
                         ROWS_PER_BLOCK * PADROW * sizeof(float));

    detect_kernel<<<1, 1024>>>((const unsigned*)candA, (const unsigned*)candB);
    setup_kernel<<<1, 1024>>>((const float*)candA, (const float*)candB);
    main_kernel<<<N_BLOCKS, 256, ROWS_PER_BLOCK * PADROW * sizeof(float)>>>(logits, candA, candB);
    finish_kernel<<<1, 256>>>(out);
}

// round 7
// speedup vs baseline: 1.1094x; 1.1094x over previous
#include <cuda_runtime.h>
#include <cuda_bf16.h>
#include <cstdint>

#define FULLMASK 0xffffffffu
#define F_DIM 1024
#define C_DIM 64
#define N_ROWS 65536           // 32*2048
#define PADROW 3008            // 1024 + 64*31 worst-case alignment padding

// ---- scratch (device globals; no allocation) ----
__device__ __align__(16) unsigned short g_perm16[F_DIM]; // f -> padded position (fits 16b)
__device__ int g_base[C_DIM];    // segment -> padded base offset (base % 32 == 4s % 32)
__device__ int g_len[C_DIM];     // segment -> length
__device__ int g_wlmax[8];       // warp w -> max len among segments 8w..8w+7
__device__ int g_labIsA;         // 1 if candidate A is the labels buffer
__device__ int g_lab64;          // 1 if labels are 64-bit
__device__ float g_terms[N_ROWS];

// ============================================================
// Detect: disambiguate labels vs mask among the two 65536-elem
// buffers, and label width (int32 vs int64). One block.
//   mask one-hot: ~98% zero words; int64 labels ~51%; int32 ~1.6%.
//   Odd-word OR == 0  <=>  int64 labels.
// ============================================================
__global__ void detect_kernel(const unsigned* __restrict__ A,
                              const unsigned* __restrict__ B) {
    __shared__ int sh[32];
    int t = threadIdx.x, lane = t & 31, wid = t >> 5;

    int zA = 0, zB = 0;
    unsigned oA = 0u, oB = 0u;
    for (int i = t; i < 8192; i += 1024) {
        unsigned wa = A[i], wb = B[i];
        zA += (wa == 0u); zB += (wb == 0u);
        if (i & 1) { oA |= wa; oB |= wb; }
    }
#pragma unroll
    for (int o = 16; o; o >>= 1) {
        zA += __shfl_xor_sync(FULLMASK, zA, o);
        zB += __shfl_xor_sync(FULLMASK, zB, o);
        oA |= __shfl_xor_sync(FULLMASK, oA, o);
        oB |= __shfl_xor_sync(FULLMASK, oB, o);
    }
    if (lane == 0) sh[wid] = zA;
    __syncthreads();
    if (t == 0) { int s = 0; for (int i = 0; i < 32; i++) s += sh[i]; sh[0] = s; }
    __syncthreads();
    int zAt = sh[0];
    __syncthreads();
    if (lane == 0) sh[wid] = (int)(oA != 0u);
    __syncthreads();
    if (t == 0) { int s = 0; for (int i = 0; i < 32; i++) s |= sh[i]; sh[0] = s; }
    __syncthreads();
    int oAt = sh[0];
    __syncthreads();
    if (lane == 0) sh[wid] = (int)(oB != 0u);
    __syncthreads();
    if (t == 0) { int s = 0; for (int i = 0; i < 32; i++) s |= sh[i]; sh[0] = s; }
    __syncthreads();
    int oBt = sh[0];

    if (t == 0) {
        int aIsMask = (zAt > 6000);           // mask ~8064 zero words of 8192
        g_labIsA = aIsMask ? 0 : 1;
        int labOdd = aIsMask ? oBt : oAt;     // odd-word OR of the labels buffer
        g_lab64 = (labOdd == 0) ? 1 : 0;      // high words all zero => int64
    }
}

// ============================================================
// Setup: seg ids, counts, bank-aligned bases (base % 32 == 4s % 32),
// uint16 scatter permutation, per-warp max lengths. One block.
// ============================================================
__global__ void setup_kernel(const float* __restrict__ candA,
                             const float* __restrict__ candB) {
    __shared__ int sh_seg[F_DIM];
    __shared__ int sh_cnt[C_DIM];
    __shared__ int sh_base[C_DIM];

    const float* mask = g_labIsA ? candB : candA;

    int tid = threadIdx.x;
    if (tid < C_DIM) sh_cnt[tid] = 0;
    __syncthreads();

    int wid = tid >> 5, lane = tid & 31;
    // warp per fine row of mask: find one-hot column via ballot
    for (int f = wid; f < F_DIM; f += 32) {
        float v0 = mask[f * C_DIM + lane];
        float v1 = mask[f * C_DIM + 32 + lane];
        unsigned b0 = __ballot_sync(FULLMASK, v0 > 0.5f);
        unsigned b1 = __ballot_sync(FULLMASK, v1 > 0.5f);
        int c = b0 ? (__ffs(b0) - 1) : (32 + __ffs(b1) - 1);
        if (lane == 0) { sh_seg[f] = c; atomicAdd(&sh_cnt[c], 1); }
    }
    __syncthreads();

    // bases in natural order; segment s aligned so base % 32 == (4s) % 32
    if (tid == 0) {
        int b = 0;
        for (int s = 0; s < C_DIM; s++) {
            int tgt = (4 * s) & 31;
            int pad = (tgt - (b & 31) + 32) & 31;
            int bb = b + pad;
            sh_base[s] = bb;
            b = bb + sh_cnt[s];
        }
    }
    __syncthreads();

    // deterministic scatter positions (uint16)
    if (tid < C_DIM) {
        int p = sh_base[tid];
        for (int f = 0; f < F_DIM; f++) {
            if (sh_seg[f] == tid) g_perm16[f] = (unsigned short)(p++);
        }
        g_base[tid] = sh_base[tid];
        g_len[tid]  = sh_cnt[tid];
    }
    if (tid < 8) {
        int mx = 0;
        for (int k = 0; k < 8; k++) mx = max(mx, sh_cnt[tid * 8 + k]);
        g_wlmax[tid] = mx;
    }
}

// ============================================================
// Main: 1 block (256 threads) = 1 row. 4 threads per segment.
// Conflict-free stride-4 scans (base%32==4s%32), quad shfl combine,
// tiny block reductions. ~12.6KB smem -> 8 blocks/SM, 64 warps/SM.
// ============================================================
__global__ void __launch_bounds__(256, 8)
main_kernel(const float* __restrict__ logits,
            const void* __restrict__ candA, const void* __restrict__ candB) {
    __shared__ float buf[PADROW];
    __shared__ float smax[C_DIM];
    __shared__ float ssum[C_DIM];
    __shared__ float sh_m;
    __shared__ int   sh_lab;

    int row = blockIdx.x;
    int t = threadIdx.x;
    int w = t >> 5, lane = t & 31;
    int s = t >> 2, j = t & 3;

    // prefetch label early (overlaps staging)
    if (t == 0) {
        const void* labp = g_labIsA ? candA : candB;
        sh_lab = g_lab64 ? (int)((const long long*)labp)[row]
                         : ((const int*)labp)[row];
    }

    // stage: coalesced float4 load + uint16-perm scatter into smem
    const float4*  src4 = (const float4*)(logits + (size_t)row * F_DIM);
    float4  v = src4[t];
    ushort4 p = ((const ushort4*)g_perm16)[t];
    buf[p.x] = v.x; buf[p.y] = v.y; buf[p.z] = v.z; buf[p.w] = v.w;

    int len = g_len[s];
    int bas = g_base[s];
    int wl  = g_wlmax[w];
    __syncthreads();

    // pass 1: per-segment max; lanes hit distinct banks every step
    float ms = -3.4e38f;
    for (int i = j; i < wl; i += 4)
        if (i < len) ms = fmaxf(ms, buf[bas + i]);
    ms = fmaxf(ms, __shfl_xor_sync(FULLMASK, ms, 1));
    ms = fmaxf(ms, __shfl_xor_sync(FULLMASK, ms, 2));
    if (j == 0) smax[s] = ms;
    __syncthreads();

    // warp 0: global row max
    if (t < 32) {
        float a = fmaxf(smax[t], smax[t + 32]);
#pragma unroll
        for (int o = 16; o; o >>= 1) a = fmaxf(a, __shfl_xor_sync(FULLMASK, a, o));
        if (t == 0) sh_m = a;
    }
    __syncthreads();
    float m = sh_m;

    // pass 2: per-segment sum of exp(v - m)
    float es = 0.f;
    for (int i = j; i < wl; i += 4)
        if (i < len) es += __expf(buf[bas + i] - m);
    es += __shfl_xor_sync(FULLMASK, es, 1);
    es += __shfl_xor_sync(FULLMASK, es, 2);
    if (j == 0) ssum[s] = es;
    __syncthreads();

    // warp 0: totals + label terms
    if (t < 32) {
        float e  = ssum[t] + ssum[t + 32];
        float gg = __expf(smax[t] - m) + __expf(smax[t + 32] - m);
#pragma unroll
        for (int o = 16; o; o >>= 1) {
            e  += __shfl_xor_sync(FULLMASK, e, o);
            gg += __shfl_xor_sync(FULLMASK, gg, o);
        }
        if (t == 0) {
            int lab = sh_lab;
            float cl = smax[lab], sl = ssum[lab];
            g_terms[row] = (cl - m - __logf(gg)) + (__logf(sl) - __logf(e));
        }
    }
}

// ============================================================
// Finish: deterministic reduce of 65536 float terms -> scalar
// ============================================================
__global__ void finish_kernel(float* __restrict__ out) {
    __shared__ double sh[1024];
    int t = threadIdx.x;
    double s = 0.0;
    for (int i = t; i < N_ROWS; i += 1024) s += (double)g_terms[i];
    sh[t] = s;
    __syncthreads();
    for (int o = 512; o; o >>= 1) {
        if (t < o) sh[t] += sh[t + o];
        __syncthreads();
    }
    if (t == 0) out[0] = (float)(-0.5 * sh[0] / (double)N_ROWS);
}

extern "C" void kernel_launch(void* const* d_in, const int* in_sizes, int n_in,
                              void* d_out, int out_size) {
    // identify logits by element count; the other two are device-disambiguated
    int li = 0;
    for (int i = 0; i < n_in; i++) if (in_sizes[i] > 1000000) { li = i; break; }
    int o1 = (li == 0) ? 1 : 0;
    int o2 = (li == 2) ? 1 : 2;
    if (o2 == o1) o2 = (o1 == 1) ? 2 : 1;

    const float* logits = (const float*)d_in[li];
    const void*  candA  = d_in[o1];
    const void*  candB  = d_in[o2];
    float*       out    = (float*)d_out;

    detect_kernel<<<1, 1024>>>((const unsigned*)candA, (const unsigned*)candB);
    setup_kernel<<<1, 1024>>>((const float*)candA, (const float*)candB);
    main_kernel<<<N_ROWS, 256>>>(logits, candA, candB);
    finish_kernel<<<1, 1024>>>(out);
}